// round 12
// baseline (speedup 1.0000x reference)
#include <cuda_runtime.h>
#include <cstdint>

#define N_NODES 100000
#define E_EDGES 3200000
#define IN_DIM  256
#define OUT_DIM 64
#define LN_EPS  1e-5f
#define NEG_SLOPE 0.01f

// Scratch (no allocations allowed -> __device__ globals).
__device__ __align__(16) float g_deg[N_NODES];
__device__ __align__(16) float g_hs [N_NODES * OUT_DIM];  // (x@W)*rsqrt(deg[row])
__device__ __align__(16) int   g_cnt[N_NODES];            // in-degree (edge count)
__device__ __align__(16) int   g_rp [N_NODES];            // CSR row start
__device__ __align__(16) int   g_cur[N_NODES];            // build cursor
__device__ __align__(16) uint2 g_srcw[E_EDGES];           // (src, bits(w)) sorted by dst

// ---------------------------------------------------------------------------
// 1) init: deg=1 (self loop), cnt=0
// ---------------------------------------------------------------------------
__global__ void k_init() {
    int i = blockIdx.x * blockDim.x + threadIdx.x;
    if (i < N_NODES) { g_deg[i] = 1.0f; g_cnt[i] = 0; }
}

// ---------------------------------------------------------------------------
// 2) deg[dst] += ew ; cnt[dst]++    (L2-resident atomics)
// ---------------------------------------------------------------------------
__global__ void k_deg_cnt(const int* __restrict__ ei, const float* __restrict__ ew) {
    int e = blockIdx.x * blockDim.x + threadIdx.x;
    if (e < E_EDGES) {
        int d = ei[E_EDGES + e];
        atomicAdd(&g_deg[d], ew[e]);
        atomicAdd(&g_cnt[d], 1);
    }
}

// ---------------------------------------------------------------------------
// 3) exclusive scan of cnt -> rp, cur   (single block, 1024 threads)
// ---------------------------------------------------------------------------
__global__ void __launch_bounds__(1024) k_scan() {
    __shared__ int s[1024];
    const int tid = threadIdx.x;
    const int CH  = (N_NODES + 1023) / 1024;          // 98
    const int lo  = tid * CH;
    const int hi  = (lo + CH < N_NODES) ? lo + CH : N_NODES;

    int sum = 0;
    for (int i = lo; i < hi; i++) sum += g_cnt[i];
    s[tid] = sum;
    __syncthreads();
    // Hillis-Steele inclusive scan
    for (int off = 1; off < 1024; off <<= 1) {
        int v = (tid >= off) ? s[tid - off] : 0;
        __syncthreads();
        s[tid] += v;
        __syncthreads();
    }
    int run = s[tid] - sum;                            // exclusive base
    for (int i = lo; i < hi; i++) {
        g_rp[i]  = run;
        g_cur[i] = run;
        run += g_cnt[i];
    }
}

// ---------------------------------------------------------------------------
// 4) build CSR payload: srcw[pos] = (src, w), pos via cursor atomics
// ---------------------------------------------------------------------------
__global__ void k_build(const int* __restrict__ ei, const float* __restrict__ ew) {
    int e = blockIdx.x * blockDim.x + threadIdx.x;
    if (e >= E_EDGES) return;
    int   src = ei[e];
    int   dst = ei[E_EDGES + e];
    float w   = ew[e];
    int   pos = atomicAdd(&g_cur[dst], 1);
    g_srcw[pos] = make_uint2((unsigned)src, __float_as_uint(w));
}

// ---------------------------------------------------------------------------
// 5) GEMM (tf32 tensor cores, 3-term split) -> g_hs only (R7 winner, minus acc)
// ---------------------------------------------------------------------------
#define GEMM_ROWS 128
#define KC  128
#define SP  132          // padded smem stride -> frag bank = 4g+t (no conflict)
#define OSP 68

__device__ __forceinline__ uint32_t f2tf32(float f) {
    uint32_t r;
    asm("cvt.rna.tf32.f32 %0, %1;" : "=r"(r) : "f"(f));
    return r;
}

__device__ __forceinline__ void mma_tf32(float c[4], const uint32_t a[4],
                                         uint32_t b0, uint32_t b1) {
    asm volatile(
        "mma.sync.aligned.m16n8k8.row.col.f32.tf32.tf32.f32 "
        "{%0,%1,%2,%3}, {%4,%5,%6,%7}, {%8,%9}, {%0,%1,%2,%3};"
        : "+f"(c[0]), "+f"(c[1]), "+f"(c[2]), "+f"(c[3])
        : "r"(a[0]), "r"(a[1]), "r"(a[2]), "r"(a[3]), "r"(b0), "r"(b1));
}

__global__ void __launch_bounds__(256, 2) k_gemm(const float* __restrict__ x,
                                                 const float* __restrict__ W) {
    extern __shared__ float sm[];
    float* xs = sm;                       // [128][SP]
    float* wt = xs + GEMM_ROWS * SP;      // [64][SP]

    const int tid   = threadIdx.x;
    const int node0 = blockIdx.x * GEMM_ROWS;
    const int wid   = tid >> 5;
    const int lane  = tid & 31;
    const int g     = lane >> 2;
    const int t     = lane & 3;
    const int m0    = (wid & 3) * 16;
    const int nb    = (wid >> 2) * 64;

    float c[8][4];
    #pragma unroll
    for (int j = 0; j < 8; j++)
        #pragma unroll
        for (int q = 0; q < 4; q++) c[j][q] = 0.f;

    for (int ch = 0; ch < 2; ch++) {
        const int k0c = ch * KC;

        for (int i = 0; i < 8; i++) {
            int idx4 = tid + 256 * i;
            int n4   = idx4 & 15;
            int kk   = idx4 >> 4;
            float4 v = ((const float4*)W)[(size_t)(k0c + kk) * 16 + n4];
            wt[(n4 * 4 + 0) * SP + kk] = v.x;
            wt[(n4 * 4 + 1) * SP + kk] = v.y;
            wt[(n4 * 4 + 2) * SP + kk] = v.z;
            wt[(n4 * 4 + 3) * SP + kk] = v.w;
        }
        for (int i = 0; i < 16; i++) {
            int idx4 = tid + 256 * i;
            int k4   = idx4 & 31;
            int r    = idx4 >> 5;
            int gr   = node0 + r;
            float4 v = (gr < N_NODES)
                     ? ((const float4*)x)[(size_t)gr * 64 + (k0c >> 2) + k4]
                     : make_float4(0.f, 0.f, 0.f, 0.f);
            *(float4*)&xs[r * SP + k4 * 4] = v;
        }
        __syncthreads();

        #pragma unroll 4
        for (int ks = 0; ks < KC / 8; ks++) {
            const int k0 = ks * 8;
            float af[4];
            af[0] = wt[(m0 + g)     * SP + k0 + t];
            af[1] = wt[(m0 + g + 8) * SP + k0 + t];
            af[2] = wt[(m0 + g)     * SP + k0 + t + 4];
            af[3] = wt[(m0 + g + 8) * SP + k0 + t + 4];
            uint32_t ah[4], al[4];
            #pragma unroll
            for (int q = 0; q < 4; q++) {
                ah[q] = f2tf32(af[q]);
                al[q] = __float_as_uint(af[q] - __uint_as_float(ah[q]));
            }
            #pragma unroll
            for (int j = 0; j < 8; j++) {
                const int n0 = nb + j * 8;
                float b0f = xs[(n0 + g) * SP + k0 + t];
                float b1f = xs[(n0 + g) * SP + k0 + t + 4];
                uint32_t bh0 = f2tf32(b0f);
                uint32_t bh1 = f2tf32(b1f);
                uint32_t bl0 = __float_as_uint(b0f - __uint_as_float(bh0));
                uint32_t bl1 = __float_as_uint(b1f - __uint_as_float(bh1));
                mma_tf32(c[j], ah, bh0, bh1);
                mma_tf32(c[j], al, bh0, bh1);
                mma_tf32(c[j], ah, bl0, bl1);
            }
        }
        __syncthreads();
    }

    float* smo = sm;  // [128][OSP]
    #pragma unroll
    for (int j = 0; j < 8; j++) {
        const int nloc = nb + j * 8 + 2 * t;
        smo[(nloc)     * OSP + m0 + g]     = c[j][0];
        smo[(nloc + 1) * OSP + m0 + g]     = c[j][1];
        smo[(nloc)     * OSP + m0 + g + 8] = c[j][2];
        smo[(nloc + 1) * OSP + m0 + g + 8] = c[j][3];
    }
    __syncthreads();

    for (int i = 0; i < 8; i++) {
        int idx4 = tid + 256 * i;
        int r    = idx4 >> 4;
        int c4   = idx4 & 15;
        int gn   = node0 + r;
        if (gn < N_NODES) {
            float rs = rsqrtf(g_deg[gn]);
            float4 v = *(float4*)&smo[r * OSP + c4 * 4];
            v.x *= rs; v.y *= rs; v.z *= rs; v.w *= rs;
            ((float4*)g_hs)[(size_t)gn * 16 + c4] = v;
        }
    }
}

// ---------------------------------------------------------------------------
// 6) gather + finalize (fused): warp per dst node, lane owns 2 cols.
//    acc = hs[n] + sum_e w_e * hs[src_e]  (pure loads, no atomics)
//    then y = acc*dinv + b -> leaky -> LayerNorm -> out
// ---------------------------------------------------------------------------
__global__ void __launch_bounds__(256) k_gather(const float* __restrict__ b,
                                                const float* __restrict__ gamma,
                                                const float* __restrict__ beta,
                                                float* __restrict__ out) {
    int n    = (blockIdx.x * blockDim.x + threadIdx.x) >> 5;
    int lane = threadIdx.x & 31;
    if (n >= N_NODES) return;

    const int c0  = lane << 1;
    float2 acc = *(const float2*)&g_hs[n * OUT_DIM + c0];   // self-loop term

    const int beg = g_rp[n];
    const int cnt = g_cnt[n];

    #pragma unroll 4
    for (int j = 0; j < cnt; j++) {
        uint2 eo = __ldg(&g_srcw[beg + j]);                 // broadcast, L1-hit
        float w  = __uint_as_float(eo.y);
        float2 hv = *(const float2*)&g_hs[(int)eo.x * OUT_DIM + c0];
        acc.x = fmaf(w, hv.x, acc.x);
        acc.y = fmaf(w, hv.y, acc.y);
    }

    float dinv = rsqrtf(g_deg[n]);
    float y0 = acc.x * dinv + b[c0];
    float y1 = acc.y * dinv + b[c0 + 1];
    y0 = (y0 >= 0.f) ? y0 : NEG_SLOPE * y0;
    y1 = (y1 >= 0.f) ? y1 : NEG_SLOPE * y1;

    float s  = y0 + y1;
    float sq = y0 * y0 + y1 * y1;
    #pragma unroll
    for (int off = 16; off > 0; off >>= 1) {
        s  += __shfl_xor_sync(0xFFFFFFFFu, s,  off);
        sq += __shfl_xor_sync(0xFFFFFFFFu, sq, off);
    }
    float mu  = s * (1.f / 64.f);
    float var = sq * (1.f / 64.f) - mu * mu;
    float inv = rsqrtf(var + LN_EPS);

    float2 r;
    r.x = (y0 - mu) * inv * gamma[c0]     + beta[c0];
    r.y = (y1 - mu) * inv * gamma[c0 + 1] + beta[c0 + 1];
    *(float2*)&out[n * OUT_DIM + c0] = r;
}

// ---------------------------------------------------------------------------
extern "C" void kernel_launch(void* const* d_in, const int* in_sizes, int n_in,
                              void* d_out, int out_size) {
    const float* x     = (const float*)d_in[0];
    const int*   ei    = (const int*)  d_in[1];
    const float* ew    = (const float*)d_in[2];
    const float* W     = (const float*)d_in[3];
    const float* b     = (const float*)d_in[4];
    const float* gamma = (const float*)d_in[5];
    const float* beta  = (const float*)d_in[6];
    float* out = (float*)d_out;

    const int gemm_smem = (GEMM_ROWS * SP + OUT_DIM * SP) * (int)sizeof(float); // ~101KB
    cudaFuncSetAttribute(k_gemm, cudaFuncAttributeMaxDynamicSharedMemorySize, gemm_smem);

    k_init    <<<(N_NODES + 255) / 256, 256>>>();
    k_deg_cnt <<<(E_EDGES + 255) / 256, 256>>>(ei, ew);
    k_scan    <<<1, 1024>>>();
    k_build   <<<(E_EDGES + 255) / 256, 256>>>(ei, ew);
    k_gemm    <<<(N_NODES + GEMM_ROWS - 1) / GEMM_ROWS, 256, gemm_smem>>>(x, W);
    k_gather  <<<(N_NODES * 32 + 255) / 256, 256>>>(b, gamma, beta, out);
}

// round 15
// speedup vs baseline: 1.0051x; 1.0051x over previous
#include <cuda_runtime.h>
#include <cstdint>

#define N_NODES 100000
#define E_EDGES 3200000
#define IN_DIM  256
#define OUT_DIM 64
#define LN_EPS  1e-5f
#define NEG_SLOPE 0.01f

// Scratch (no allocations allowed -> __device__ globals).
__device__ __align__(16) float g_deg[N_NODES];
__device__ __align__(16) float g_hs [N_NODES * OUT_DIM];  // (x@W)*rsqrt(deg[row])
__device__ __align__(16) int   g_cnt[N_NODES];            // in-degree (edge count)
__device__ __align__(16) int   g_rp [N_NODES];            // CSR row start
__device__ __align__(16) int   g_cur[N_NODES];            // build cursor
__device__ __align__(16) uint2 g_srcw[E_EDGES];           // (src, bits(w)) grouped by dst

// ---------------------------------------------------------------------------
// 1) init: deg=1 (self loop), cnt=0
// ---------------------------------------------------------------------------
__global__ void k_init() {
    int i = blockIdx.x * blockDim.x + threadIdx.x;
    if (i < N_NODES) { g_deg[i] = 1.0f; g_cnt[i] = 0; }
}

// ---------------------------------------------------------------------------
// 2) deg[dst] += ew ; cnt[dst]++    (L2-resident atomics)
// ---------------------------------------------------------------------------
__global__ void k_deg_cnt(const int* __restrict__ ei, const float* __restrict__ ew) {
    int e = blockIdx.x * blockDim.x + threadIdx.x;
    if (e < E_EDGES) {
        int d = ei[E_EDGES + e];
        atomicAdd(&g_deg[d], ew[e]);
        atomicAdd(&g_cnt[d], 1);
    }
}

// ---------------------------------------------------------------------------
// 3) exclusive scan of cnt -> rp, cur   (single block, 1024 threads)
// ---------------------------------------------------------------------------
__global__ void __launch_bounds__(1024) k_scan() {
    __shared__ int s[1024];
    const int tid = threadIdx.x;
    const int CH  = (N_NODES + 1023) / 1024;          // 98
    const int lo  = tid * CH;
    const int hi  = (lo + CH < N_NODES) ? lo + CH : N_NODES;

    int sum = 0;
    for (int i = lo; i < hi; i++) sum += g_cnt[i];
    s[tid] = sum;
    __syncthreads();
    for (int off = 1; off < 1024; off <<= 1) {
        int v = (tid >= off) ? s[tid - off] : 0;
        __syncthreads();
        s[tid] += v;
        __syncthreads();
    }
    int run = s[tid] - sum;                            // exclusive base
    for (int i = lo; i < hi; i++) {
        g_rp[i]  = run;
        g_cur[i] = run;
        run += g_cnt[i];
    }
}

// ---------------------------------------------------------------------------
// 4) build CSR payload; 4 grid-strided edges/thread -> 4 independent ATOMG chains
// ---------------------------------------------------------------------------
__global__ void k_build(const int* __restrict__ ei, const float* __restrict__ ew) {
    const int stride = gridDim.x * blockDim.x;          // = E_EDGES/4
    int e = blockIdx.x * blockDim.x + threadIdx.x;
    #pragma unroll 4
    for (int r = 0; r < 4; r++, e += stride) {
        int   src = ei[e];
        int   dst = ei[E_EDGES + e];
        float w   = ew[e];
        int   pos = atomicAdd(&g_cur[dst], 1);
        g_srcw[pos] = make_uint2((unsigned)src, __float_as_uint(w));
    }
}

// ---------------------------------------------------------------------------
// 5) GEMM (tf32 tensor cores, 3-term split) -> g_hs (R7/R10 winner)
// ---------------------------------------------------------------------------
#define GEMM_ROWS 128
#define KC  128
#define SP  132
#define OSP 68

__device__ __forceinline__ uint32_t f2tf32(float f) {
    uint32_t r;
    asm("cvt.rna.tf32.f32 %0, %1;" : "=r"(r) : "f"(f));
    return r;
}

__device__ __forceinline__ void mma_tf32(float c[4], const uint32_t a[4],
                                         uint32_t b0, uint32_t b1) {
    asm volatile(
        "mma.sync.aligned.m16n8k8.row.col.f32.tf32.tf32.f32 "
        "{%0,%1,%2,%3}, {%4,%5,%6,%7}, {%8,%9}, {%0,%1,%2,%3};"
        : "+f"(c[0]), "+f"(c[1]), "+f"(c[2]), "+f"(c[3])
        : "r"(a[0]), "r"(a[1]), "r"(a[2]), "r"(a[3]), "r"(b0), "r"(b1));
}

__global__ void __launch_bounds__(256, 2) k_gemm(const float* __restrict__ x,
                                                 const float* __restrict__ W) {
    extern __shared__ float sm[];
    float* xs = sm;                       // [128][SP]
    float* wt = xs + GEMM_ROWS * SP;      // [64][SP]

    const int tid   = threadIdx.x;
    const int node0 = blockIdx.x * GEMM_ROWS;
    const int wid   = tid >> 5;
    const int lane  = tid & 31;
    const int g     = lane >> 2;
    const int t     = lane & 3;
    const int m0    = (wid & 3) * 16;
    const int nb    = (wid >> 2) * 64;

    float c[8][4];
    #pragma unroll
    for (int j = 0; j < 8; j++)
        #pragma unroll
        for (int q = 0; q < 4; q++) c[j][q] = 0.f;

    for (int ch = 0; ch < 2; ch++) {
        const int k0c = ch * KC;

        for (int i = 0; i < 8; i++) {
            int idx4 = tid + 256 * i;
            int n4   = idx4 & 15;
            int kk   = idx4 >> 4;
            float4 v = ((const float4*)W)[(size_t)(k0c + kk) * 16 + n4];
            wt[(n4 * 4 + 0) * SP + kk] = v.x;
            wt[(n4 * 4 + 1) * SP + kk] = v.y;
            wt[(n4 * 4 + 2) * SP + kk] = v.z;
            wt[(n4 * 4 + 3) * SP + kk] = v.w;
        }
        for (int i = 0; i < 16; i++) {
            int idx4 = tid + 256 * i;
            int k4   = idx4 & 31;
            int r    = idx4 >> 5;
            int gr   = node0 + r;
            float4 v = (gr < N_NODES)
                     ? ((const float4*)x)[(size_t)gr * 64 + (k0c >> 2) + k4]
                     : make_float4(0.f, 0.f, 0.f, 0.f);
            *(float4*)&xs[r * SP + k4 * 4] = v;
        }
        __syncthreads();

        #pragma unroll 4
        for (int ks = 0; ks < KC / 8; ks++) {
            const int k0 = ks * 8;
            float af[4];
            af[0] = wt[(m0 + g)     * SP + k0 + t];
            af[1] = wt[(m0 + g + 8) * SP + k0 + t];
            af[2] = wt[(m0 + g)     * SP + k0 + t + 4];
            af[3] = wt[(m0 + g + 8) * SP + k0 + t + 4];
            uint32_t ah[4], al[4];
            #pragma unroll
            for (int q = 0; q < 4; q++) {
                ah[q] = f2tf32(af[q]);
                al[q] = __float_as_uint(af[q] - __uint_as_float(ah[q]));
            }
            #pragma unroll
            for (int j = 0; j < 8; j++) {
                const int n0 = nb + j * 8;
                float b0f = xs[(n0 + g) * SP + k0 + t];
                float b1f = xs[(n0 + g) * SP + k0 + t + 4];
                uint32_t bh0 = f2tf32(b0f);
                uint32_t bh1 = f2tf32(b1f);
                uint32_t bl0 = __float_as_uint(b0f - __uint_as_float(bh0));
                uint32_t bl1 = __float_as_uint(b1f - __uint_as_float(bh1));
                mma_tf32(c[j], ah, bh0, bh1);
                mma_tf32(c[j], al, bh0, bh1);
                mma_tf32(c[j], ah, bl0, bl1);
            }
        }
        __syncthreads();
    }

    float* smo = sm;  // [128][OSP]
    #pragma unroll
    for (int j = 0; j < 8; j++) {
        const int nloc = nb + j * 8 + 2 * t;
        smo[(nloc)     * OSP + m0 + g]     = c[j][0];
        smo[(nloc + 1) * OSP + m0 + g]     = c[j][1];
        smo[(nloc)     * OSP + m0 + g + 8] = c[j][2];
        smo[(nloc + 1) * OSP + m0 + g + 8] = c[j][3];
    }
    __syncthreads();

    for (int i = 0; i < 8; i++) {
        int idx4 = tid + 256 * i;
        int r    = idx4 >> 4;
        int c4   = idx4 & 15;
        int gn   = node0 + r;
        if (gn < N_NODES) {
            float rs = rsqrtf(g_deg[gn]);
            float4 v = *(float4*)&smo[r * OSP + c4 * 4];
            v.x *= rs; v.y *= rs; v.z *= rs; v.w *= rs;
            ((float4*)g_hs)[(size_t)gn * 16 + c4] = v;
        }
    }
}

// ---------------------------------------------------------------------------
// 6) gather + finalize (fused), ILP-restructured:
//    2 nodes/warp; 16 lanes/node, float4/lane (one LDG.128 = 2 edges' rows).
//    Records loaded COALESCED 16-at-a-time, distributed via shfl.
//    R14 FIX: shfl hoisted out of ternary (conditional __shfl_sync deadlocked).
// ---------------------------------------------------------------------------
__global__ void __launch_bounds__(256) k_gather(const float* __restrict__ b,
                                                const float* __restrict__ gamma,
                                                const float* __restrict__ beta,
                                                float* __restrict__ out) {
    const int warp = (blockIdx.x * blockDim.x + threadIdx.x) >> 5;
    const int lane = threadIdx.x & 31;
    const int hl   = lane & 15;           // lane within half-warp
    const int half = lane >> 4;           // 0 or 1 -> which node
    const int n    = warp * 2 + half;
    const bool valid = (n < N_NODES);

    int beg = 0, cnt = 0;
    float4 acc = make_float4(0.f, 0.f, 0.f, 0.f);
    const int c0 = hl << 2;               // 4 cols per lane
    if (valid) {
        beg = g_rp[n];
        cnt = g_cnt[n];
        acc = *(const float4*)&g_hs[n * OUT_DIM + c0];   // self-loop term
    }

    // warp-uniform trip count (UNCONDITIONAL shfl, then max in registers)
    const int other  = __shfl_xor_sync(0xFFFFFFFFu, cnt, 16);
    const int maxcnt = (cnt > other) ? cnt : other;

    for (int base = 0; base < maxcnt; base += 16) {
        int j = base + hl;
        uint2 rec = (valid && j < cnt) ? g_srcw[beg + j] : make_uint2(0u, 0u);

        #pragma unroll 4
        for (int k = 0; k < 16; k++) {
            int slane = (half << 4) | k;  // record holder for this half's edge k
            unsigned sb = __shfl_sync(0xFFFFFFFFu, rec.x, slane);
            unsigned wb = __shfl_sync(0xFFFFFFFFu, rec.y, slane);
            if (base + k < cnt) {
                float  w  = __uint_as_float(wb);
                float4 hv = *(const float4*)&g_hs[(int)sb * OUT_DIM + c0];
                acc.x = fmaf(w, hv.x, acc.x);
                acc.y = fmaf(w, hv.y, acc.y);
                acc.z = fmaf(w, hv.z, acc.z);
                acc.w = fmaf(w, hv.w, acc.w);
            }
        }
    }

    if (!valid) return;

    float dinv = rsqrtf(g_deg[n]);
    float y0 = acc.x * dinv + b[c0];
    float y1 = acc.y * dinv + b[c0 + 1];
    float y2 = acc.z * dinv + b[c0 + 2];
    float y3 = acc.w * dinv + b[c0 + 3];
    y0 = (y0 >= 0.f) ? y0 : NEG_SLOPE * y0;
    y1 = (y1 >= 0.f) ? y1 : NEG_SLOPE * y1;
    y2 = (y2 >= 0.f) ? y2 : NEG_SLOPE * y2;
    y3 = (y3 >= 0.f) ? y3 : NEG_SLOPE * y3;

    float s  = y0 + y1 + y2 + y3;
    float sq = y0 * y0 + y1 * y1 + y2 * y2 + y3 * y3;
    #pragma unroll
    for (int off = 8; off > 0; off >>= 1) {   // reduce within 16-lane half
        s  += __shfl_xor_sync(0xFFFFFFFFu, s,  off);
        sq += __shfl_xor_sync(0xFFFFFFFFu, sq, off);
    }
    float mu  = s * (1.f / 64.f);
    float var = sq * (1.f / 64.f) - mu * mu;
    float inv = rsqrtf(var + LN_EPS);

    float4 r;
    r.x = (y0 - mu) * inv * gamma[c0]     + beta[c0];
    r.y = (y1 - mu) * inv * gamma[c0 + 1] + beta[c0 + 1];
    r.z = (y2 - mu) * inv * gamma[c0 + 2] + beta[c0 + 2];
    r.w = (y3 - mu) * inv * gamma[c0 + 3] + beta[c0 + 3];
    *(float4*)&out[n * OUT_DIM + c0] = r;
}

// ---------------------------------------------------------------------------
extern "C" void kernel_launch(void* const* d_in, const int* in_sizes, int n_in,
                              void* d_out, int out_size) {
    const float* x     = (const float*)d_in[0];
    const int*   ei    = (const int*)  d_in[1];
    const float* ew    = (const float*)d_in[2];
    const float* W     = (const float*)d_in[3];
    const float* b     = (const float*)d_in[4];
    const float* gamma = (const float*)d_in[5];
    const float* beta  = (const float*)d_in[6];
    float* out = (float*)d_out;

    const int gemm_smem = (GEMM_ROWS * SP + OUT_DIM * SP) * (int)sizeof(float); // ~101KB
    cudaFuncSetAttribute(k_gemm, cudaFuncAttributeMaxDynamicSharedMemorySize, gemm_smem);

    k_init    <<<(N_NODES + 255) / 256, 256>>>();
    k_deg_cnt <<<(E_EDGES + 255) / 256, 256>>>(ei, ew);
    k_scan    <<<1, 1024>>>();
    k_build   <<<(E_EDGES / 4 + 255) / 256, 256>>>(ei, ew);   // 4 edges/thread
    k_gemm    <<<(N_NODES + GEMM_ROWS - 1) / GEMM_ROWS, 256, gemm_smem>>>(x, W);
    // 2 nodes per warp -> 50000 warps -> 6250 blocks of 256
    k_gather  <<<(N_NODES / 2 * 32 + 255) / 256, 256>>>(b, gamma, beta, out);
}